// round 12
// baseline (speedup 1.0000x reference)
#include <cuda_runtime.h>

#define GH 96
#define GW 96
#define HW (GH*GW)
#define BSZ 8
#define LN 16
#define PN 16
#define NCELL (BSZ*GH*GW)   /* 73728 */
#define TPB 128
#define NBLK (NCELL/TPB)    /* 576 */

__device__ float g_partials[NBLK];
__device__ unsigned int g_ticket;   // zero-init; last block resets it

typedef unsigned long long u64;

__device__ __forceinline__ float asqrt(float x) {
    float r;
    asm("sqrt.approx.f32 %0, %1;" : "=f"(r) : "f"(x));
    return r;
}
__device__ __forceinline__ float arcp(float x) {
    float r;
    asm("rcp.approx.f32 %0, %1;" : "=f"(r) : "f"(x));
    return r;
}
__device__ __forceinline__ u64 pk2(float a, float b) {
    u64 r; asm("mov.b64 %0, {%1, %2};" : "=l"(r) : "f"(a), "f"(b)); return r;
}
__device__ __forceinline__ void upk2(float& a, float& b, u64 v) {
    asm("mov.b64 {%0, %1}, %2;" : "=f"(a), "=f"(b) : "l"(v));
}
__device__ __forceinline__ u64 add2(u64 a, u64 b) {
    u64 r; asm("add.rn.f32x2 %0, %1, %2;" : "=l"(r) : "l"(a), "l"(b)); return r;
}
__device__ __forceinline__ u64 mul2(u64 a, u64 b) {
    u64 r; asm("mul.rn.f32x2 %0, %1, %2;" : "=l"(r) : "l"(a), "l"(b)); return r;
}
__device__ __forceinline__ u64 fma2(u64 a, u64 b, u64 c) {
    u64 r; asm("fma.rn.f32x2 %0, %1, %2, %3;" : "=l"(r) : "l"(a), "l"(b), "l"(c)); return r;
}

__global__ __launch_bounds__(TPB, 3)
void yolino_main(const float* __restrict__ target, const float* __restrict__ pred,
                 float* __restrict__ out)
{
    const int n = blockIdx.x * TPB + threadIdx.x;   // n in [0, NCELL)
    const int w  = n % GW;
    const int t1 = n / GW;
    const int h  = t1 % GH;
    const int b  = t1 / GH;

    const float* tb = target + b * (64 * HW) + h * GW + w;
    const float* pb = pred   + b * (96 * HW) + h * GW + w;

    // 16 target lines, packed per-line endpoint pairs: tx=(x1,x2), ty=(y1,y2).
    u64 tx[LN], ty[LN];
    unsigned tmask = 0;
    #pragma unroll
    for (int l = 0; l < LN; ++l) {
        float x1 = tb[(l * 4 + 0) * HW];
        float y1 = tb[(l * 4 + 1) * HW];
        float x2 = tb[(l * 4 + 2) * HW];
        float y2 = tb[(l * 4 + 3) * HW];
        tx[l] = pk2(x1, x2);
        ty[l] = pk2(y1, y2);
        float s = (x1 + y1) + (x2 + y2);
        if (s > 0.f) tmask |= (1u << l);
    }

    float loss = 0.f;

    // Prefetch predictors 0 and 1 (two independent 6-channel buffers).
    float qa[6], qb[6];
    {
        const float* na = pb;
        const float* nb = pb + 6 * HW;
        #pragma unroll
        for (int j = 0; j < 6; ++j) { qa[j] = na[j * HW]; qb[j] = nb[j * HW]; }
    }

    #pragma unroll 1
    for (int pi = 0; pi < PN; pi += 2) {
        // Consume both prefetch buffers.
        const float a0 = qa[0], a1 = qa[1], a2 = qa[2],
                    a3 = qa[3], a4 = qa[4], a5 = qa[5];
        const float b0 = qb[0], b1 = qb[1], b2 = qb[2],
                    b3 = qb[3], b4 = qb[4], b5 = qb[5];

        // Refill for pi+2 / pi+3.
        if (pi + 2 < PN) {
            const float* na = pb + (pi + 2) * (6 * HW);
            const float* nb = pb + (pi + 3) * (6 * HW);
            #pragma unroll
            for (int j = 0; j < 6; ++j) { qa[j] = na[j * HW]; qb[j] = nb[j * HW]; }
        }

        const u64 ncxA = pk2(-a0, -a2), ncyA = pk2(-a1, -a3);
        const u64 ncxB = pk2(-b0, -b2), ncyB = pk2(-b1, -b3);

        // Pass 1: both predictors' 16 distances, interleaved per line —
        // two independent dependency streams per l keep the pipes fed.
        float dA[LN], dB[LN];
        #pragma unroll
        for (int l = 0; l < LN; ++l) {
            u64 dxA = add2(tx[l], ncxA);
            u64 dyA = add2(ty[l], ncyA);
            u64 dxB = add2(tx[l], ncxB);
            u64 dyB = add2(ty[l], ncyB);
            u64 sA  = fma2(dxA, dxA, mul2(dyA, dyA));
            u64 sB  = fma2(dxB, dxB, mul2(dyB, dyB));
            float sA1, sA2, sB1, sB2;
            upk2(sA1, sA2, sA);
            upk2(sB1, sB2, sB);
            dA[l] = asqrt(sA1) + asqrt(sA2);
            dB[l] = asqrt(sB1) + asqrt(sB2);
        }

        // Pass 2: two tree mins (independent).
        float ma, mb;
        {
            float mm[8];
            #pragma unroll
            for (int i = 0; i < 8; ++i) mm[i] = fminf(dA[2*i], dA[2*i+1]);
            #pragma unroll
            for (int i = 0; i < 4; ++i) mm[i] = fminf(mm[i], mm[i+4]);
            mm[0] = fminf(mm[0], mm[2]); mm[1] = fminf(mm[1], mm[3]);
            ma = fminf(mm[0], mm[1]);
        }
        {
            float mm[8];
            #pragma unroll
            for (int i = 0; i < 8; ++i) mm[i] = fminf(dB[2*i], dB[2*i+1]);
            #pragma unroll
            for (int i = 0; i < 4; ++i) mm[i] = fminf(mm[i], mm[i+4]);
            mm[0] = fminf(mm[0], mm[2]); mm[1] = fminf(mm[1], mm[3]);
            mb = fminf(mm[0], mm[1]);
        }

        // Pass 3: tie masks (4 independent OR chains).
        unsigned aA0 = 0, aA1 = 0, aB0 = 0, aB1 = 0;
        #pragma unroll
        for (int i = 0; i < 8; ++i) {
            aA0 |= (dA[i]     == ma) ? (1u << i)       : 0u;
            aA1 |= (dA[i + 8] == ma) ? (1u << (i + 8)) : 0u;
            aB0 |= (dB[i]     == mb) ? (1u << i)       : 0u;
            aB1 |= (dB[i + 8] == mb) ? (1u << (i + 8)) : 0u;
        }

        const float cntA = (ma < 2.f) ? (float)__popc((aA0 | aA1) & tmask) : 0.f;
        const float cntB = (mb < 2.f) ? (float)__popc((aB0 | aB1) & tmask) : 0.f;

        // dist terms.
        loss = fmaf(ma, cntA, loss);
        loss = fmaf(mb, cntB, loss);

        // Confidence terms.
        float sigA = arcp(1.f + __expf(-a4));
        float sigB = arcp(1.f + __expf(-b4));
        float eA   = (cntA > 0.f) ? (sigA - 1.f) : sigA;
        float eB   = (cntB > 0.f) ? (sigB - 1.f) : sigB;
        loss = fmaf(eA, eA, loss);
        loss = fmaf(eB, eB, loss);

        // Class terms: cls_hard = 1 <=> conf-logit > 0.
        if (!(a5 > 0.f)) loss += cntA;
        if (!(b5 > 0.f)) loss += cntB;
    }

    // ---- block reduction (deterministic) ----
    #pragma unroll
    for (int o = 16; o > 0; o >>= 1)
        loss += __shfl_xor_sync(0xffffffffu, loss, o);

    __shared__ float sw[TPB / 32];
    __shared__ bool  s_last;
    const int lane = threadIdx.x & 31;
    const int wid  = threadIdx.x >> 5;
    if (lane == 0) sw[wid] = loss;
    __syncthreads();
    if (wid == 0) {
        float v = (lane < TPB / 32) ? sw[lane] : 0.f;
        #pragma unroll
        for (int o = 2; o > 0; o >>= 1)
            v += __shfl_xor_sync(0xffffffffu, v, o);
        if (lane == 0) {
            g_partials[blockIdx.x] = v;
            __threadfence();
            unsigned t = atomicAdd(&g_ticket, 1u);
            s_last = (t == NBLK - 1);
        }
    }
    __syncthreads();

    // ---- last block folds all partials into the output ----
    if (s_last) {
        __threadfence();  // acquire: make all g_partials visible
        const int t = threadIdx.x;
        float v = 0.f;
        for (int i = t; i < NBLK; i += TPB)   // fixed order: deterministic
            v += g_partials[i];
        __shared__ float s[TPB];
        s[t] = v;
        __syncthreads();
        #pragma unroll
        for (int o = TPB / 2; o > 0; o >>= 1) {
            if (t < o) s[t] += s[t + o];
            __syncthreads();
        }
        if (t == 0) {
            out[0] = s[0] * (1.0f / BSZ);
            g_ticket = 0;   // reset for the next (graph-replayed) launch
        }
    }
}

extern "C" void kernel_launch(void* const* d_in, const int* in_sizes, int n_in,
                              void* d_out, int out_size)
{
    const float* target = (const float*)d_in[0];
    const float* pred   = (const float*)d_in[1];
    float* out = (float*)d_out;

    yolino_main<<<NBLK, TPB>>>(target, pred, out);
}